// round 17
// baseline (speedup 1.0000x reference)
#include <cuda_runtime.h>
#include <cuda_fp16.h>
#include <cstdint>

#define D_FEAT    128
#define MAX_NODES 65536
#define MAX_EDGES 1100000
#define BIN_CAP   96        // slots per node; Poisson(16) max-degree << 96
#define CVT_PER_THREAD 4    // float4s converted per thread

// ---------------- static device scratch (allocation-free) -------------------
// g_cursor[MAX_NODES] doubles as the overflow counter so ONE memset node
// resets all per-replay state.
__device__ int  g_cursor[MAX_NODES + 1];
__device__ int2 g_slots[MAX_NODES * BIN_CAP];   // {src, float_as_int(val)}
__device__ int  g_over_edges[MAX_EDGES];
__device__ __align__(16) __half g_feat16[MAX_NODES * D_FEAT];   // 16.8 MB

// ---------------------------------------------------------------------------
// 1) FUSED fill + convert, interleaved block roles (proven R12-R15 config).
// ---------------------------------------------------------------------------
__global__ void fill_convert_kernel(const int*    __restrict__ src,
                                    const int*    __restrict__ dst,
                                    const float*  __restrict__ vals,
                                    const float4* __restrict__ feat4,
                                    int n_edges, int total4,
                                    int eb, int nb)
{
    int b = blockIdx.x;
    long long eprev = ((long long)b * eb) / nb;
    bool is_edge = (((long long)(b + 1) * eb) / nb) > eprev;

    if (is_edge) {
        int i = (int)eprev * blockDim.x + threadIdx.x;
        if (i < n_edges) {
            int d   = __ldg(&dst[i]);
            int s   = __ldg(&src[i]);
            float v = __ldg(&vals[i]);
            int pos = atomicAdd(&g_cursor[d], 1);
            if (pos < BIN_CAP)
                g_slots[d * BIN_CAP + pos] = make_int2(s, __float_as_int(v));
            else
                g_over_edges[atomicAdd(&g_cursor[MAX_NODES], 1)] = i;
        }
    } else {
        int cblk = b - (int)eprev;
        int base = cblk * blockDim.x * CVT_PER_THREAD;
        uint2* out16 = reinterpret_cast<uint2*>(g_feat16);
        #pragma unroll
        for (int k = 0; k < CVT_PER_THREAD; ++k) {
            int c = base + k * blockDim.x + threadIdx.x;
            if (c < total4) {
                float4 f = __ldg(&feat4[c]);
                __half2 lo = __floats2half2_rn(f.x, f.y);
                __half2 hi = __floats2half2_rn(f.z, f.w);
                uint2 packed;
                packed.x = *reinterpret_cast<uint32_t*>(&lo);
                packed.y = *reinterpret_cast<uint32_t*>(&hi);
                out16[c] = packed;
            }
        }
    }
}

// ---------------------------------------------------------------------------
// helper: accumulate v * (8 halves in uint4) into acc[0..7]
// ---------------------------------------------------------------------------
__device__ __forceinline__ void acc8(float* acc, uint4 h, float v) {
    __half2* hh = reinterpret_cast<__half2*>(&h);
    #pragma unroll
    for (int j = 0; j < 4; ++j) {
        float2 f = __half22float2(hh[j]);
        acc[2 * j]     = fmaf(v, f.x, acc[2 * j]);
        acc[2 * j + 1] = fmaf(v, f.y, acc[2 * j + 1]);
    }
}

// ---------------------------------------------------------------------------
// 2) warp-per-node gather, HALF-WARP EDGE PAIRING:
//    lanes 0-15 process edge e, lanes 16-31 edge e+1 — one LDG.128 covers
//    two edges' rows, halving the per-edge shfl/LDG/loop warp-instruction
//    count (gather is instruction-throughput bound: issue 61%, no unit
//    saturated). Cross-half shfl_xor reduction + bias at the end.
//    READ-ONLY on scratch, NO fences (proven constraints).
// ---------------------------------------------------------------------------
__global__ void gather_kernel(const float4* __restrict__ bias4,
                              float4* __restrict__ out4,
                              const int*   __restrict__ src,
                              const int*   __restrict__ dst,
                              const float* __restrict__ vals,
                              int n_rows)
{
    int gtid = blockIdx.x * blockDim.x + threadIdx.x;
    int node = gtid >> 5;
    int lane = gtid & 31;
    if (node >= n_rows) return;

    int half = lane >> 4;        // 0: even edge of pair, 1: odd edge
    int sub  = lane & 15;        // owns 8 feature cols [sub*8, sub*8+8)

    const uint4* f16q = reinterpret_cast<const uint4*>(g_feat16);

    float acc[8] = {0.f, 0.f, 0.f, 0.f, 0.f, 0.f, 0.f, 0.f};

    int cnt = g_cursor[node];
    cnt = min(cnt, BIN_CAP);
    const int2* bin = g_slots + (size_t)node * BIN_CAP;

    // lane-parallel slot fetch (proven R12): one coalesced 256B load
    int2 myslot = make_int2(0, 0);
    if (lane < cnt) myslot = __ldg(&bin[lane]);

    int n0 = min(cnt, 32);
    int e = 0;

    // main: 2 pairs (4 edges) per iteration, 2 independent LDG.128s
    for (; e + 3 < n0; e += 4) {
        int i0 = e + half;
        int i1 = e + 2 + half;
        int   s0 = __shfl_sync(0xffffffffu, myslot.x, i0);
        float v0 = __int_as_float(__shfl_sync(0xffffffffu, myslot.y, i0));
        int   s1 = __shfl_sync(0xffffffffu, myslot.x, i1);
        float v1 = __int_as_float(__shfl_sync(0xffffffffu, myslot.y, i1));
        uint4 h0 = __ldg(&f16q[(size_t)s0 * 16 + sub]);
        uint4 h1 = __ldg(&f16q[(size_t)s1 * 16 + sub]);
        acc8(acc, h0, v0);
        acc8(acc, h1, v1);
    }
    // one remaining full pair
    for (; e + 1 < n0; e += 2) {
        int i0 = e + half;
        int   s0 = __shfl_sync(0xffffffffu, myslot.x, i0);
        float v0 = __int_as_float(__shfl_sync(0xffffffffu, myslot.y, i0));
        uint4 h0 = __ldg(&f16q[(size_t)s0 * 16 + sub]);
        acc8(acc, h0, v0);
    }
    // odd tail edge: half 1 contributes zero (xor-reduce stays exact)
    if (e < n0) {
        int   s0 = __shfl_sync(0xffffffffu, myslot.x, e);
        float v0 = __int_as_float(__shfl_sync(0xffffffffu, myslot.y, e));
        if (half) v0 = 0.0f;
        uint4 h0 = __ldg(&f16q[(size_t)s0 * 16 + sub]);
        acc8(acc, h0, v0);
    }
    // rare: degree > 32 (P ~ 2e-4 per node) — uniform slots, half-gated
    for (int e2 = 32; e2 < cnt; ++e2) {
        int2 sv = __ldg(&bin[e2]);
        float v = __int_as_float(sv.y);
        if (half) v = 0.0f;
        uint4 h = __ldg(&f16q[(size_t)sv.x * 16 + sub]);
        acc8(acc, h, v);
    }

    // overflow drain (0 in practice: P(deg>96) ~ 1e-40 for this dataset)
    int oc = g_cursor[MAX_NODES];
    if (oc != 0) {
        for (int i = 0; i < oc; ++i) {
            int eid = g_over_edges[i];
            if (__ldg(&dst[eid]) == node) {
                float v = __ldg(&vals[eid]);
                if (half) v = 0.0f;
                int s = __ldg(&src[eid]);
                uint4 h = __ldg(&f16q[(size_t)s * 16 + sub]);
                acc8(acc, h, v);
            }
        }
    }

    // cross-half reduction: combine even-edge and odd-edge partial sums
    #pragma unroll
    for (int k = 0; k < 8; ++k)
        acc[k] += __shfl_xor_sync(0xffffffffu, acc[k], 16);

    // lanes 0-15 add bias and store their 8 columns (2 x float4)
    if (half == 0) {
        float4 b0 = __ldg(&bias4[sub * 2]);
        float4 b1 = __ldg(&bias4[sub * 2 + 1]);
        float4 o0 = make_float4(acc[0] + b0.x, acc[1] + b0.y,
                                acc[2] + b0.z, acc[3] + b0.w);
        float4 o1 = make_float4(acc[4] + b1.x, acc[5] + b1.y,
                                acc[6] + b1.z, acc[7] + b1.w);
        out4[(size_t)node * 32 + sub * 2]     = o0;
        out4[(size_t)node * 32 + sub * 2 + 1] = o1;
    }
}

// ---------------------------------------------------------------------------
// Fallback (R1 proven path, full fp32) for shapes exceeding static scratch
// ---------------------------------------------------------------------------
__global__ void init_bias_kernel(float4* __restrict__ out,
                                 const float4* __restrict__ bias4,
                                 int total_vec4) {
    int idx = blockIdx.x * blockDim.x + threadIdx.x;
    if (idx >= total_vec4) return;
    out[idx] = __ldg(&bias4[idx & 31]);
}

__global__ void spmm_edge_kernel(const int* __restrict__ src,
                                 const int* __restrict__ dst,
                                 const float* __restrict__ vals,
                                 const float* __restrict__ feat,
                                 float* __restrict__ out,
                                 int n_edges) {
    int gtid = blockIdx.x * blockDim.x + threadIdx.x;
    int edge = gtid >> 5;
    int lane = gtid & 31;
    if (edge >= n_edges) return;

    int s = 0, d = 0;
    float v = 0.0f;
    if (lane == 0) { s = src[edge]; d = dst[edge]; v = vals[edge]; }
    s = __shfl_sync(0xffffffffu, s, 0);
    d = __shfl_sync(0xffffffffu, d, 0);
    v = __shfl_sync(0xffffffffu, v, 0);

    const float4* frow = reinterpret_cast<const float4*>(feat + (size_t)s * D_FEAT);
    float4 f = __ldg(&frow[lane]);
    float4 m = make_float4(f.x * v, f.y * v, f.z * v, f.w * v);

    float* orow = out + (size_t)d * D_FEAT + lane * 4;
    asm volatile("red.global.add.v4.f32 [%0], {%1, %2, %3, %4};"
                 :: "l"(orow), "f"(m.x), "f"(m.y), "f"(m.z), "f"(m.w)
                 : "memory");
}

// ---------------------------------------------------------------------------
// Launch.  d_in[0]=edge_index(2E i32: src then dst)  d_in[1]=edge_vals(E f32)
//          d_in[2]=features(N*128 f32)               d_in[3]=bias(128 f32)
// ---------------------------------------------------------------------------
extern "C" void kernel_launch(void* const* d_in, const int* in_sizes, int n_in,
                              void* d_out, int out_size)
{
    const int*   edge_index = (const int*)d_in[0];
    const float* edge_vals  = (const float*)d_in[1];
    const float* features   = (const float*)d_in[2];
    const float* bias       = (const float*)d_in[3];
    float*       out        = (float*)d_out;

    int n_edges = in_sizes[1];
    int n_rows  = in_sizes[2] / D_FEAT;

    const int* src = edge_index;
    const int* dst = edge_index + n_edges;

    if (n_rows <= MAX_NODES && n_edges <= MAX_EDGES) {
        {   // 1) reset cursors + overflow counter: ONE memset graph node
            void* cur_ptr = nullptr;
            cudaGetSymbolAddress(&cur_ptr, g_cursor);
            cudaMemsetAsync(cur_ptr, 0, (size_t)(MAX_NODES + 1) * sizeof(int), 0);
        }
        {   // 2) fused fill + fp16 convert
            int th = 256;
            int total4 = n_rows * (D_FEAT / 4);
            int eb = (n_edges + th - 1) / th;
            int cb = (total4 + th * CVT_PER_THREAD - 1) / (th * CVT_PER_THREAD);
            int nb = eb + cb;
            fill_convert_kernel<<<nb, th>>>(src, dst, edge_vals,
                                            (const float4*)features,
                                            n_edges, total4, eb, nb);
        }
        {   // 3) gather (warp per node), half-warp edge pairing
            int th = 256;
            long long total = (long long)n_rows * 32;
            int bl = (int)((total + th - 1) / th);
            gather_kernel<<<bl, th>>>((const float4*)bias,
                                      (float4*)out,
                                      src, dst, edge_vals, n_rows);
        }
    } else {
        {   // fallback: bias init + atomic scatter (full fp32)
            int total_vec4 = n_rows * (D_FEAT / 4);
            int th = 256, bl = (total_vec4 + th - 1) / th;
            init_bias_kernel<<<bl, th>>>((float4*)out, (const float4*)bias,
                                         total_vec4);
        }
        {
            int th = 256;
            long long total = (long long)n_edges * 32;
            int bl = (int)((total + th - 1) / th);
            spmm_edge_kernel<<<bl, th>>>(src, dst, edge_vals, features, out,
                                         n_edges);
        }
    }
}